// round 13
// baseline (speedup 1.0000x reference)
#include <cuda_runtime.h>
#include <cuda_fp16.h>
#include <math.h>
#include <stdint.h>

#define NM    512
#define NT    64
#define NH1   256
#define NH2   128
#define STEPS 20
#define NBLK  96          // 12 clusters x 8 CTAs; bids 0..7 = compute cluster, 8..95 = formation
#define NTHR  512
#define CLN   8
#define NTAY  3           // residual ~3e-5; measured chain: NTAY4 -> rel 2.2e-6 contribution
#define NM4   (NM * NM / 4)
#define FBLK  (NBLK - CLN)   // 88 formation blocks
#define BPS   11             // formation blocks per 64-row slice
#define CT    24             // fp16 terms kept L1-resident via __ldg (24*745*8B ~ 143KB)

// ----------------- device scratch (allocation is forbidden) -----------------
__device__ __align__(16) float g_Omega[NM * NM];
__device__ __align__(16) __half g_omh[64 * NM * NM];   // fp16 shadow of omegas (33.5MB)
__device__ float g_softv[STEPS][NT];
__device__ int   g_softn[STEPS];               // NT active, -1 skipped (done)
__device__ unsigned g_soft_seq;                // step s published when == s+1
__device__ unsigned g_sdone[STEPS][CLN];       // per-slice formation arrivals (11 each)
__device__ unsigned g_cnt, g_gen;              // init grid barrier (replay-safe)

// ----------------------------- ptx helpers ----------------------------------
__device__ __forceinline__ unsigned smem_u32(const void* p) {
    unsigned r;
    asm("{ .reg .u64 t; cvta.to.shared.u64 t, %1; cvt.u32.u64 %0, t; }"
        : "=r"(r) : "l"(p));
    return r;
}
__device__ __forceinline__ unsigned mapa_u32(unsigned a, unsigned rank) {
    unsigned r;
    asm("mapa.shared::cluster.u32 %0, %1, %2;" : "=r"(r) : "r"(a), "r"(rank));
    return r;
}
// one-sided remote store: data + tx-signal on the SAME remote CTA's mbarrier
__device__ __forceinline__ void st_async_b32(unsigned dst, unsigned val, unsigned mbar) {
    asm volatile("st.async.shared::cluster.mbarrier::complete_tx::bytes.b32 [%0], %1, [%2];"
                 :: "r"(dst), "r"(val), "r"(mbar) : "memory");
}
// scoped release/acquire — NO membar.gl, NO CCTL.IVALL (L1 stays warm)
__device__ __forceinline__ void st_release_gpu(unsigned* p, unsigned v) {
    asm volatile("st.release.gpu.global.u32 [%0], %1;" :: "l"(p), "r"(v) : "memory");
}
__device__ __forceinline__ unsigned ld_acquire_gpu(const unsigned* p) {
    unsigned v;
    asm volatile("ld.acquire.gpu.global.u32 %0, [%1];" : "=r"(v) : "l"(p) : "memory");
    return v;
}
__device__ __forceinline__ void red_release_gpu_add(unsigned* p, unsigned v) {
    asm volatile("red.release.gpu.global.add.u32 [%0], %1;" :: "l"(p), "r"(v) : "memory");
}
__device__ __forceinline__ float4 hf2f4(uint2 u) {
    __half2 lo = *reinterpret_cast<__half2*>(&u.x);
    __half2 hi = *reinterpret_cast<__half2*>(&u.y);
    const float2 a = __half22float2(lo), b = __half22float2(hi);
    return make_float4(a.x, a.y, b.x, b.y);
}
#define MBARRIER_INIT(addr, count) \
    asm volatile("mbarrier.init.shared.b64 [%0], %1;" :: "r"(addr), "r"(count) : "memory")
#define MBARRIER_EXPECT_TX(addr, bytes) \
    asm volatile("mbarrier.arrive.expect_tx.shared.b64 _, [%0], %1;" \
                 :: "r"(addr), "r"(bytes) : "memory")
#define MBARRIER_WAIT_PARITY(addr, parity) do { \
    unsigned _mb = (addr), _par = (unsigned)(parity), _done; \
    asm volatile("{\n\t.reg .pred p;\n\t" \
        "mbarrier.try_wait.parity.acquire.cta.shared::cta.b64 p, [%1], %2;\n\t" \
        "selp.b32 %0, 1, 0, p;\n\t}" : "=r"(_done) : "r"(_mb), "r"(_par) : "memory"); \
    if (!_done) { \
        asm volatile("{\n\t.reg .pred P1;\n\t" \
            "WL_%=:\n\t" \
            "mbarrier.try_wait.parity.acquire.cta.shared::cta.b64 P1, [%0], %1, 0x989680;\n\t" \
            "@P1 bra.uni WD_%=;\n\t" \
            "bra.uni WL_%=;\n\t" \
            "WD_%=:\n\t}" :: "r"(_mb), "r"(_par) : "memory"); \
    } \
} while (0)
#define CLUSTER_SYNC() do { \
    asm volatile("barrier.cluster.arrive.aligned;" ::: "memory"); \
    asm volatile("barrier.cluster.wait.aligned;"   ::: "memory"); } while (0)

// One grid barrier per launch (init only — its fences/flushes are pre-scan).
__device__ __forceinline__ void grid_sync() {
    __syncthreads();
    if (threadIdx.x == 0) {
        __threadfence();
        unsigned gen = *(volatile unsigned*)&g_gen;
        if (atomicAdd(&g_cnt, 1u) == NBLK - 1u) {
            g_cnt = 0u;
            __threadfence();
            *(volatile unsigned*)&g_gen = gen + 1u;
        } else {
            while (*(volatile unsigned*)&g_gen == gen) { }
        }
        __threadfence();
    }
    __syncthreads();
}

__global__ void __launch_bounds__(NTHR, 1) __cluster_dims__(CLN, 1, 1)
petri_kernel(const float* __restrict__ v_src,  const float* __restrict__ v_target,
             const float* __restrict__ omegas, const float* __restrict__ W1,
             const float* __restrict__ b1,     const float* __restrict__ W2,
             const float* __restrict__ b2,     const float* __restrict__ W3,
             const float* __restrict__ b3,     const float* __restrict__ gumbel,
             float* __restrict__ out)
{
    __shared__ __align__(16) float s_t[2][NM];   // Taylor ping-pong (exchange buffers)
    __shared__ __align__(16) float s_v[NM];      // state (replicated in cluster)
    __shared__ __align__(16) float s_p[8 * NH1]; // MLP partial staging
    __shared__ float s_hg[CLN * NH1];            // L1 partials gathered in CTA0
    __shared__ float s_h1t[NH1];                 // precomputed v_target @ W1-half
    __shared__ float s_h1[NH1];
    __shared__ float s_h2[NH2];
    __shared__ float s_brd[64];                  // Taylor broadcast staging
    __shared__ float s_sm[NT];
    __shared__ float s_fv[NT];
    __shared__ float s_wred[16];
    __shared__ int   s_wri[16];
    __shared__ int   s_done, s_n, s_tgt;
    __shared__ float s_scal;
    __shared__ __align__(8) unsigned long long s_mbX[2];  // exchange mbarriers
    __shared__ __align__(8) unsigned long long s_mbA;     // phase-A gather mbarrier

    const int tid  = threadIdx.x;
    const int bid  = blockIdx.x;
    const int lane = tid & 31;
    const int warp = tid >> 5;
    const bool incl = (bid < CLN);
    const int  rank = bid;

    const float4* W14 = (const float4*)W1;
    const float4* W24 = (const float4*)W2;
    const float4* W34 = (const float4*)W3;

    int ph0 = 0, ph1 = 0, phA = 0;               // mbarrier parity trackers

    // ---------------- per-launch reset (ordered by the single grid barrier) ----------------
    if (bid == 0 && tid == 0) {
        g_soft_seq = 0u;
        for (int s = 0; s < STEPS; ++s)
            for (int r = 0; r < CLN; ++r) g_sdone[s][r] = 0u;
    }

    // ---- one-time fp16 conversion of omegas (all 96 blocks; replay-identical) ----
    {
        const float4* src = (const float4*)omegas;
        uint2* dst = (uint2*)g_omh;
        for (int i = bid * NTHR + tid; i < 64 * NM4; i += NBLK * NTHR) {
            const float4 w = __ldcs(src + i);
            __half2 lo = __floats2half2_rn(w.x, w.y);
            __half2 hi = __floats2half2_rn(w.z, w.w);
            uint2 u;
            u.x = *reinterpret_cast<unsigned*>(&lo);
            u.y = *reinterpret_cast<unsigned*>(&hi);
            dst[i] = u;
        }
    }

    if (incl) {
        s_v[tid] = v_src[tid];
        if (tid == 0) {
            s_done = 0;
            MBARRIER_INIT(smem_u32(&s_mbX[0]), 1u);
            MBARRIER_INIT(smem_u32(&s_mbX[1]), 1u);
            MBARRIER_INIT(smem_u32(&s_mbA), 1u);
            MBARRIER_EXPECT_TX(smem_u32(&s_mbX[0]), 2048u);
            MBARRIER_EXPECT_TX(smem_u32(&s_mbX[1]), 2048u);
            if (rank == 0) MBARRIER_EXPECT_TX(smem_u32(&s_mbA), 8192u);
        }
        // tgt = argmax(v_target), first-index tie-break
        {
            float bv = v_target[tid]; int bi = tid;
            #pragma unroll
            for (int off = 16; off > 0; off >>= 1) {
                float ov = __shfl_down_sync(0xffffffffu, bv, off);
                int   oi = __shfl_down_sync(0xffffffffu, bi, off);
                if (ov > bv) { bv = ov; bi = oi; }
            }
            if (lane == 0) { s_wred[warp] = bv; s_wri[warp] = bi; }
        }
        __syncthreads();
        if (tid == 0) {
            float mv = s_wred[0]; int mi = s_wri[0];
            #pragma unroll
            for (int w = 1; w < 16; ++w)
                if (s_wred[w] > mv) { mv = s_wred[w]; mi = s_wri[w]; }
            s_tgt = mi;
        }
        // precompute target half of MLP L1: rows 512+64r .. 512+64r+64 of W1
        {
            const int u = tid & 63, part = tid >> 6;   // 8 parts x 8 rows
            float4 a = make_float4(0.f, 0.f, 0.f, 0.f);
            #pragma unroll
            for (int ii = 0; ii < 8; ++ii) {
                const int vr  = 64 * rank + part * 8 + ii;
                const float x = v_target[vr];
                const float4 w = __ldcs(&W14[(size_t)(NM + vr) * 64 + u]);  // no L1 pollution
                a.x += x * w.x; a.y += x * w.y; a.z += x * w.z; a.w += x * w.w;
            }
            ((float4*)s_p)[part * 64 + u] = a;
        }
        __syncthreads();
        if (tid < NH1) {
            float pj = 0.f;
            #pragma unroll
            for (int r = 0; r < 8; ++r) pj += s_p[r * NH1 + tid];
            s_p[tid] = pj;                 // stage for cluster exchange below
        }
        CLUSTER_SYNC();                    // mbarrier inits visible cluster-wide
        // one-time broadcast of target-half L1 partials into every CTA's s_hg row
        if (tid < NH1) {
            #pragma unroll
            for (int r = 0; r < CLN; ++r) {
                unsigned dst = mapa_u32(smem_u32(&s_hg[rank * NH1 + tid]), (unsigned)r);
                asm volatile("st.shared::cluster.f32 [%0], %1;" :: "r"(dst), "f"(s_p[tid]) : "memory");
            }
        }
        CLUSTER_SYNC();
        if (tid < NH1) {
            float h = 0.f;
            #pragma unroll
            for (int r = 0; r < CLN; ++r) h += s_hg[r * NH1 + tid];
            s_h1t[tid] = h;
        }
        CLUSTER_SYNC();                    // protect s_hg before step-0 reuse
    }
    grid_sync();   // publishes fp16 conversion + flag resets (last L1 flush of the launch)

    // ------------------------------------ scan ------------------------------------
    // Steady state has ZERO gpu-scope fences -> no CCTL.IVALL -> L1 (weights,
    // biases, gumbel, resident omega strips) stays warm across all 20 steps.
    for (int s = 0; s < STEPS; ++s) {
        if (incl) {
            const int dn = s_done;               // done at step entry
            if (!dn) {
                // ---- (A) MLP L1, v half: CTA r covers v rows [64r, 64r+64) ----
                {
                    const int u = tid & 63, part = tid >> 6;
                    float4 a = make_float4(0.f, 0.f, 0.f, 0.f);
                    #pragma unroll
                    for (int ii = 0; ii < 8; ++ii) {
                        const int vr  = 64 * rank + part * 8 + ii;
                        const float x = s_v[vr];
                        const float4 w = __ldg(&W14[(size_t)vr * 64 + u]);   // L1 hit after step 0
                        a.x += x * w.x; a.y += x * w.y; a.z += x * w.z; a.w += x * w.w;
                    }
                    ((float4*)s_p)[part * 64 + u] = a;
                }
                __syncthreads();
                if (tid < NH1) {               // one-sided push into CTA0 + tx signal
                    float pj = 0.f;
                    #pragma unroll
                    for (int r = 0; r < 8; ++r) pj += s_p[r * NH1 + tid];
                    unsigned dst = mapa_u32(smem_u32(&s_hg[rank * NH1 + tid]), 0u);
                    unsigned mb  = mapa_u32(smem_u32(&s_mbA), 0u);
                    st_async_b32(dst, __float_as_uint(pj), mb);
                }
                // ranks 1..7 do NOT wait — they fall through to the soft poll.

                // ---- (B) MLP tail + gumbel softmax + publish (CTA0 only) ----
                if (rank == 0) {
                    MBARRIER_WAIT_PARITY(smem_u32(&s_mbA), phA);
                    phA ^= 1;
                    if (tid == 0) MBARRIER_EXPECT_TX(smem_u32(&s_mbA), 8192u);
                    __syncthreads();
                    if (tid < NH1) {
                        float h = __ldg(&b1[tid]) + s_h1t[tid];
                        #pragma unroll
                        for (int r = 0; r < CLN; ++r) h += s_hg[r * NH1 + tid];
                        s_h1[tid] = fmaxf(h, 0.f);
                    }
                    __syncthreads();
                    {   // L2: 128 outs x 256 in, 16 parts x 16 rows  (W2 in L1)
                        const int u = tid & 31, part = tid >> 5;
                        float4 a = make_float4(0.f, 0.f, 0.f, 0.f);
                        #pragma unroll
                        for (int ii = 0; ii < 16; ++ii) {
                            const int i = part * 16 + ii;
                            const float hv = s_h1[i];
                            const float4 w = __ldg(&W24[(size_t)i * 32 + u]);
                            a.x += hv * w.x; a.y += hv * w.y; a.z += hv * w.z; a.w += hv * w.w;
                        }
                        ((float4*)s_p)[part * 32 + u] = a;
                    }
                    __syncthreads();
                    if (tid < NH2) {
                        float h = __ldg(&b2[tid]);
                        #pragma unroll
                        for (int p = 0; p < 16; ++p) h += s_p[p * NH2 + tid];
                        s_h2[tid] = fmaxf(h, 0.f);
                    }
                    __syncthreads();
                    {   // L3: 64 outs x 128 in, 32 parts x 4 rows  (W3 in L1)
                        const int u = tid & 15, part = tid >> 4;
                        float4 a = make_float4(0.f, 0.f, 0.f, 0.f);
                        #pragma unroll
                        for (int ii = 0; ii < 4; ++ii) {
                            const int i = part * 4 + ii;
                            const float hv = s_h2[i];
                            const float4 w = __ldg(&W34[(size_t)i * 16 + u]);
                            a.x += hv * w.x; a.y += hv * w.y; a.z += hv * w.z; a.w += hv * w.w;
                        }
                        ((float4*)s_p)[part * 16 + u] = a;
                    }
                    __syncthreads();
                    if (tid < NT) {
                        float lg = __ldg(&b3[tid]);
                        #pragma unroll
                        for (int p = 0; p < 32; ++p) lg += s_p[p * NT + tid];
                        out[NM + s * NT + tid] = lg;                    // not done here
                        s_sm[tid] = lg + __ldg(&gumbel[s * NT + tid]);  // TAU = 1
                    }
                    __syncthreads();
                    if (tid < 32) {   // parallel max
                        float m = fmaxf(s_sm[tid], s_sm[tid + 32]);
                        #pragma unroll
                        for (int off = 16; off > 0; off >>= 1)
                            m = fmaxf(m, __shfl_xor_sync(0xffffffffu, m, off));
                        if (tid == 0) s_scal = m;
                    }
                    __syncthreads();
                    if (tid < NT) s_sm[tid] = __expf(s_sm[tid] - s_scal);
                    __syncthreads();
                    if (tid < 32) {   // parallel sum
                        float ssum = s_sm[tid] + s_sm[tid + 32];
                        #pragma unroll
                        for (int off = 16; off > 0; off >>= 1)
                            ssum += __shfl_xor_sync(0xffffffffu, ssum, off);
                        if (tid == 0) s_scal = 1.f / ssum;
                    }
                    __syncthreads();
                    if (tid < NT) g_softv[s][tid] = s_sm[tid] * s_scal;
                    __syncthreads();   // HB: all g_softv stores precede the release below
                    if (tid == 0) {
                        g_softn[s] = NT;
                        st_release_gpu(&g_soft_seq, (unsigned)(s + 1));  // release publish
                    }
                }
            } else {
                // ---- done: zero logits, frozen v, publish skip ----
                if (rank == 0) {
                    if (tid < NT) out[NM + s * NT + tid] = 0.f;
                    if (s == STEPS - 1) out[tid] = s_v[tid];
                    __syncthreads();
                    if (tid == 0) {
                        g_softn[s] = -1;
                        st_release_gpu(&g_soft_seq, (unsigned)(s + 1));
                    }
                }
            }
        }

        // ---- wait for soft publication (all blocks): acquire poll, no fence ----
        if (tid == 0) {
            while (ld_acquire_gpu(&g_soft_seq) < (unsigned)(s + 1)) { }
            s_n = __ldcg(&g_softn[s]);
        }
        __syncthreads();
        const int n = s_n;

        // ---- Omega formation: 88 non-cluster blocks, fp16 operands, fp32 accumulate ----
        // Terms 0..CT-1 via __ldg stay L1-resident across steps; CT..63 stream (__ldcs).
        if (n >= 0 && !incl) {
            if (tid < NT) s_fv[tid] = __ldcg(&g_softv[s][tid]);
            __syncthreads();
            const int b2i   = bid - CLN;              // 0..87
            const int slice = b2i / BPS, w = b2i % BPS;
            const int base  = slice * 8192 + w * 744 + (w < 8 ? w : 8);
            const int cnt   = 744 + (w < 8 ? 1 : 0);
            const uint2* ob = (const uint2*)g_omh;
            for (int e = base + tid; e < base + cnt; e += NTHR) {
                float4 a0 = make_float4(0.f, 0.f, 0.f, 0.f);
                float4 a1 = a0, a2 = a0, a3 = a0;
                #pragma unroll
                for (int q = 0; q < CT; q += 4) {           // L1-resident strips
                    const float c0 = s_fv[q],     c1 = s_fv[q + 1];
                    const float c2 = s_fv[q + 2], c3 = s_fv[q + 3];
                    const float4 w0 = hf2f4(__ldg(ob + (size_t)(q)     * NM4 + e));
                    const float4 w1 = hf2f4(__ldg(ob + (size_t)(q + 1) * NM4 + e));
                    const float4 w2 = hf2f4(__ldg(ob + (size_t)(q + 2) * NM4 + e));
                    const float4 w3 = hf2f4(__ldg(ob + (size_t)(q + 3) * NM4 + e));
                    a0.x += c0 * w0.x; a0.y += c0 * w0.y; a0.z += c0 * w0.z; a0.w += c0 * w0.w;
                    a1.x += c1 * w1.x; a1.y += c1 * w1.y; a1.z += c1 * w1.z; a1.w += c1 * w1.w;
                    a2.x += c2 * w2.x; a2.y += c2 * w2.y; a2.z += c2 * w2.z; a2.w += c2 * w2.w;
                    a3.x += c3 * w3.x; a3.y += c3 * w3.y; a3.z += c3 * w3.z; a3.w += c3 * w3.w;
                }
                #pragma unroll
                for (int q = CT; q < NT; q += 4) {          // streaming strips
                    const float c0 = s_fv[q],     c1 = s_fv[q + 1];
                    const float c2 = s_fv[q + 2], c3 = s_fv[q + 3];
                    const float4 w0 = hf2f4(__ldcs(ob + (size_t)(q)     * NM4 + e));
                    const float4 w1 = hf2f4(__ldcs(ob + (size_t)(q + 1) * NM4 + e));
                    const float4 w2 = hf2f4(__ldcs(ob + (size_t)(q + 2) * NM4 + e));
                    const float4 w3 = hf2f4(__ldcs(ob + (size_t)(q + 3) * NM4 + e));
                    a0.x += c0 * w0.x; a0.y += c0 * w0.y; a0.z += c0 * w0.z; a0.w += c0 * w0.w;
                    a1.x += c1 * w1.x; a1.y += c1 * w1.y; a1.z += c1 * w1.z; a1.w += c1 * w1.w;
                    a2.x += c2 * w2.x; a2.y += c2 * w2.y; a2.z += c2 * w2.z; a2.w += c2 * w2.w;
                    a3.x += c3 * w3.x; a3.y += c3 * w3.y; a3.z += c3 * w3.z; a3.w += c3 * w3.w;
                }
                a0.x += a1.x + a2.x + a3.x; a0.y += a1.y + a2.y + a3.y;
                a0.z += a1.z + a2.z + a3.z; a0.w += a1.w + a2.w + a3.w;
                ((float4*)g_Omega)[e] = a0;
            }
            __syncthreads();                       // all stores issued block-wide
            if (tid == 0) red_release_gpu_add(&g_sdone[s][slice], 1u);  // release arrival
        }

        // ---- Taylor action from registers (cluster 0, active steps only) ----
        if (incl && n >= 0) {
            if (tid == 0) {   // own 64-row slice ready (11 release-arrivals): acquire poll
                while (ld_acquire_gpu(&g_sdone[s][rank]) < (unsigned)BPS) { }
            }
            __syncthreads();
            float4 O[4][4];   // rows 64*rank + warp*4 + rr, cols lane*4 + 128*q
            {
                const float4* G4 = (const float4*)g_Omega;
                const int rbase = 64 * rank + warp * 4;
                #pragma unroll
                for (int rr = 0; rr < 4; ++rr)
                    #pragma unroll
                    for (int q = 0; q < 4; ++q)
                        O[rr][q] = __ldcg(&G4[(size_t)(rbase + rr) * 128 + lane + 32 * q]);
            }
            float accv = s_v[tid];

            #pragma unroll
            for (int k = 1; k <= NTAY; ++k) {
                const float4* src4 = (k == 1) ? (const float4*)s_v
                                              : (const float4*)s_t[(k - 1) & 1];
                const float4 t0 = src4[lane], t1 = src4[lane + 32],
                             t2 = src4[lane + 64], t3 = src4[lane + 96];
                const float invk = 1.0f / (float)k;
                #pragma unroll
                for (int rr = 0; rr < 4; ++rr) {
                    float p = O[rr][0].x * t0.x + O[rr][0].y * t0.y + O[rr][0].z * t0.z + O[rr][0].w * t0.w
                            + O[rr][1].x * t1.x + O[rr][1].y * t1.y + O[rr][1].z * t1.z + O[rr][1].w * t1.w
                            + O[rr][2].x * t2.x + O[rr][2].y * t2.y + O[rr][2].z * t2.z + O[rr][2].w * t2.w
                            + O[rr][3].x * t3.x + O[rr][3].y * t3.y + O[rr][3].z * t3.z + O[rr][3].w * t3.w;
                    #pragma unroll
                    for (int off = 16; off > 0; off >>= 1)
                        p += __shfl_down_sync(0xffffffffu, p, off);
                    if (lane == 0) s_brd[warp * 4 + rr] = p * invk;
                }
                __syncthreads();          // s_brd ready AND all reads of src4 done
                {   // one-sided exchange: value s_brd[m] -> rank (tid>>6), tx-signaled
                    const int m = tid & 63;
                    const unsigned dr = (unsigned)(tid >> 6);
                    const int buf = k & 1;
                    unsigned dst = mapa_u32(smem_u32(&s_t[buf][64 * rank + m]), dr);
                    unsigned mb  = mapa_u32(smem_u32(&s_mbX[buf]), dr);
                    st_async_b32(dst, __float_as_uint(s_brd[m]), mb);
                }
                {
                    const int buf = k & 1;
                    MBARRIER_WAIT_PARITY(smem_u32(&s_mbX[buf]), (buf ? ph1 : ph0));
                    if (buf) ph1 ^= 1; else ph0 ^= 1;
                    if (tid == 0) MBARRIER_EXPECT_TX(smem_u32(&s_mbX[buf]), 2048u);
                }
                __syncthreads();
                accv += s_t[k & 1][tid];
            }

            // ---- done_new = (argmax(v_new)==tgt); v = v_new (done was 0) ----
            const float vn = accv;
            {
                float bv = vn; int bi = tid;
                #pragma unroll
                for (int off = 16; off > 0; off >>= 1) {
                    float ov = __shfl_down_sync(0xffffffffu, bv, off);
                    int   oi = __shfl_down_sync(0xffffffffu, bi, off);
                    if (ov > bv) { bv = ov; bi = oi; }
                }
                if (lane == 0) { s_wred[warp] = bv; s_wri[warp] = bi; }
            }
            __syncthreads();
            s_v[tid] = vn;
            if (tid == 0) {
                float mv = s_wred[0]; int mi = s_wri[0];
                #pragma unroll
                for (int w = 1; w < 16; ++w)
                    if (s_wred[w] > mv) { mv = s_wred[w]; mi = s_wri[w]; }
                if (mi == s_tgt) s_done = 1;
            }
            __syncthreads();
            if (rank == 0 && s == STEPS - 1) out[tid] = vn;   // v_final
        }
    }
}

extern "C" void kernel_launch(void* const* d_in, const int* in_sizes, int n_in,
                              void* d_out, int out_size) {
    (void)in_sizes; (void)n_in; (void)out_size;
    const float* v_src    = (const float*)d_in[0];
    const float* v_target = (const float*)d_in[1];
    const float* omegas   = (const float*)d_in[2];
    const float* W1       = (const float*)d_in[3];
    const float* b1       = (const float*)d_in[4];
    const float* W2       = (const float*)d_in[5];
    const float* b2       = (const float*)d_in[6];
    const float* W3       = (const float*)d_in[7];
    const float* b3       = (const float*)d_in[8];
    const float* gumbel   = (const float*)d_in[9];
    float* out = (float*)d_out;

    petri_kernel<<<NBLK, NTHR>>>(v_src, v_target, omegas, W1, b1,
                                 W2, b2, W3, b3, gumbel, out);
}

// round 14
// speedup vs baseline: 1.4442x; 1.4442x over previous
#include <cuda_runtime.h>
#include <cuda_fp16.h>
#include <math.h>
#include <stdint.h>

#define NM    512
#define NT    64
#define NH1   256
#define NH2   128
#define STEPS 20
#define NBLK  96          // 12 clusters x 8 CTAs; bids 0..7 = compute cluster, 8..95 = formation
#define NTHR  512
#define CLN   8
#define NTAY  3           // measured rel_err 1.36e-4 at NTAY=3 (R13) — 7x margin
#define NM4   (NM * NM / 4)
#define FBLK  (NBLK - CLN)   // 88 formation blocks
#define BPS   11             // formation blocks per 64-row slice
#define CT    32             // fp16 terms kept L1-resident via __ldg (32*745*8B ~ 190KB)

// ----------------- device scratch (allocation is forbidden) -----------------
__device__ __align__(16) float g_Omega[NM * NM];
__device__ __align__(16) __half g_omh[64 * NM * NM];   // fp16 shadow of omegas (33.5MB)
__device__ float g_softv[STEPS][NT];
__device__ int   g_softn[STEPS];               // NT active, -1 skipped (done)
__device__ unsigned g_soft_seq;                // step s published when == s+1
__device__ unsigned g_sdone[STEPS][CLN];       // per-slice formation arrivals (11 each)
__device__ unsigned g_cnt, g_gen;              // init grid barrier (replay-safe)

// ----------------------------- ptx helpers ----------------------------------
__device__ __forceinline__ unsigned smem_u32(const void* p) {
    unsigned r;
    asm("{ .reg .u64 t; cvta.to.shared.u64 t, %1; cvt.u32.u64 %0, t; }"
        : "=r"(r) : "l"(p));
    return r;
}
__device__ __forceinline__ unsigned mapa_u32(unsigned a, unsigned rank) {
    unsigned r;
    asm("mapa.shared::cluster.u32 %0, %1, %2;" : "=r"(r) : "r"(a), "r"(rank));
    return r;
}
// one-sided remote store: data + tx-signal on the SAME remote CTA's mbarrier
__device__ __forceinline__ void st_async_b32(unsigned dst, unsigned val, unsigned mbar) {
    asm volatile("st.async.shared::cluster.mbarrier::complete_tx::bytes.b32 [%0], %1, [%2];"
                 :: "r"(dst), "r"(val), "r"(mbar) : "memory");
}
__device__ __forceinline__ float4 hf2f4(uint2 u) {
    __half2 lo = *reinterpret_cast<__half2*>(&u.x);
    __half2 hi = *reinterpret_cast<__half2*>(&u.y);
    const float2 a = __half22float2(lo), b = __half22float2(hi);
    return make_float4(a.x, a.y, b.x, b.y);
}
#define MBARRIER_INIT(addr, count) \
    asm volatile("mbarrier.init.shared.b64 [%0], %1;" :: "r"(addr), "r"(count) : "memory")
#define MBARRIER_EXPECT_TX(addr, bytes) \
    asm volatile("mbarrier.arrive.expect_tx.shared.b64 _, [%0], %1;" \
                 :: "r"(addr), "r"(bytes) : "memory")
#define MBARRIER_WAIT_PARITY(addr, parity) do { \
    unsigned _mb = (addr), _par = (unsigned)(parity), _done; \
    asm volatile("{\n\t.reg .pred p;\n\t" \
        "mbarrier.try_wait.parity.acquire.cta.shared::cta.b64 p, [%1], %2;\n\t" \
        "selp.b32 %0, 1, 0, p;\n\t}" : "=r"(_done) : "r"(_mb), "r"(_par) : "memory"); \
    if (!_done) { \
        asm volatile("{\n\t.reg .pred P1;\n\t" \
            "WL_%=:\n\t" \
            "mbarrier.try_wait.parity.acquire.cta.shared::cta.b64 P1, [%0], %1, 0x989680;\n\t" \
            "@P1 bra.uni WD_%=;\n\t" \
            "bra.uni WL_%=;\n\t" \
            "WD_%=:\n\t}" :: "r"(_mb), "r"(_par) : "memory"); \
    } \
} while (0)
#define CLUSTER_SYNC() do { \
    asm volatile("barrier.cluster.arrive.aligned;" ::: "memory"); \
    asm volatile("barrier.cluster.wait.aligned;"   ::: "memory"); } while (0)

__device__ __forceinline__ void grid_sync() {
    __syncthreads();
    if (threadIdx.x == 0) {
        __threadfence();
        unsigned gen = *(volatile unsigned*)&g_gen;
        if (atomicAdd(&g_cnt, 1u) == NBLK - 1u) {
            g_cnt = 0u;
            __threadfence();
            *(volatile unsigned*)&g_gen = gen + 1u;
        } else {
            while (*(volatile unsigned*)&g_gen == gen) { }
        }
        __threadfence();
    }
    __syncthreads();
}

__global__ void __launch_bounds__(NTHR, 1) __cluster_dims__(CLN, 1, 1)
petri_kernel(const float* __restrict__ v_src,  const float* __restrict__ v_target,
             const float* __restrict__ omegas, const float* __restrict__ W1,
             const float* __restrict__ b1,     const float* __restrict__ W2,
             const float* __restrict__ b2,     const float* __restrict__ W3,
             const float* __restrict__ b3,     const float* __restrict__ gumbel,
             float* __restrict__ out)
{
    __shared__ __align__(16) float s_t[2][NM];   // Taylor ping-pong (exchange buffers)
    __shared__ __align__(16) float s_v[NM];      // state (replicated in cluster)
    __shared__ __align__(16) float s_p[8 * NH1]; // MLP partial staging
    __shared__ float s_hg[CLN * NH1];            // L1 partials gathered in CTA0
    __shared__ float s_h1t[NH1];                 // precomputed v_target @ W1-half
    __shared__ float s_h1[NH1];
    __shared__ float s_h2[NH2];
    __shared__ float s_brd[64];                  // Taylor broadcast staging
    __shared__ float s_sm[NT];
    __shared__ float s_fv[NT];
    __shared__ float s_wred[16];
    __shared__ int   s_wri[16];
    __shared__ int   s_done, s_n, s_tgt;
    __shared__ float s_scal;
    __shared__ __align__(8) unsigned long long s_mbX[2];  // exchange mbarriers
    __shared__ __align__(8) unsigned long long s_mbA;     // phase-A gather mbarrier

    const int tid  = threadIdx.x;
    const int bid  = blockIdx.x;
    const int lane = tid & 31;
    const int warp = tid >> 5;
    const bool incl = (bid < CLN);
    const int  rank = bid;

    const float4* W14 = (const float4*)W1;
    const float4* W24 = (const float4*)W2;
    const float4* W34 = (const float4*)W3;

    int ph0 = 0, ph1 = 0, phA = 0;               // mbarrier parity trackers

    // ---------------- per-launch reset (ordered by the single grid barrier) ----------------
    if (bid == 0 && tid == 0) {
        g_soft_seq = 0u;
        for (int s = 0; s < STEPS; ++s)
            for (int r = 0; r < CLN; ++r) g_sdone[s][r] = 0u;
    }

    // ---- one-time fp16 conversion of omegas (all 96 blocks; replay-identical) ----
    {
        const float4* src = (const float4*)omegas;
        uint2* dst = (uint2*)g_omh;
        for (int i = bid * NTHR + tid; i < 64 * NM4; i += NBLK * NTHR) {
            const float4 w = __ldcs(src + i);
            __half2 lo = __floats2half2_rn(w.x, w.y);
            __half2 hi = __floats2half2_rn(w.z, w.w);
            uint2 u;
            u.x = *reinterpret_cast<unsigned*>(&lo);
            u.y = *reinterpret_cast<unsigned*>(&hi);
            dst[i] = u;
        }
    }

    if (incl) {
        s_v[tid] = v_src[tid];
        if (tid == 0) {
            s_done = 0;
            MBARRIER_INIT(smem_u32(&s_mbX[0]), 1u);
            MBARRIER_INIT(smem_u32(&s_mbX[1]), 1u);
            MBARRIER_INIT(smem_u32(&s_mbA), 1u);
            MBARRIER_EXPECT_TX(smem_u32(&s_mbX[0]), 2048u);
            MBARRIER_EXPECT_TX(smem_u32(&s_mbX[1]), 2048u);
            if (rank == 0) MBARRIER_EXPECT_TX(smem_u32(&s_mbA), 8192u);
        }
        // ---- L1 warm: pin per-step weights in this SM's L1 ----
        {
            float warm = 0.f;
            const float4* w1s = W14 + (size_t)(64 * rank) * 64;      // my v-half W1 rows
            for (int i = tid; i < 4096; i += NTHR) {
                const float4 w = __ldg(w1s + i); warm += w.x + w.y + w.z + w.w;
            }
            if (rank == 0) {
                for (int i = tid; i < 8192; i += NTHR) {             // W2
                    const float4 w = __ldg(W24 + i); warm += w.x + w.y + w.z + w.w;
                }
                for (int i = tid; i < 2048; i += NTHR) {             // W3
                    const float4 w = __ldg(W34 + i); warm += w.x + w.y + w.z + w.w;
                }
            }
            if (__float_as_uint(warm) == 0xdeadbeefu) s_scal = warm; // unprovable sink
        }
        // tgt = argmax(v_target), first-index tie-break
        {
            float bv = v_target[tid]; int bi = tid;
            #pragma unroll
            for (int off = 16; off > 0; off >>= 1) {
                float ov = __shfl_down_sync(0xffffffffu, bv, off);
                int   oi = __shfl_down_sync(0xffffffffu, bi, off);
                if (ov > bv) { bv = ov; bi = oi; }
            }
            if (lane == 0) { s_wred[warp] = bv; s_wri[warp] = bi; }
        }
        __syncthreads();
        if (tid == 0) {
            float mv = s_wred[0]; int mi = s_wri[0];
            #pragma unroll
            for (int w = 1; w < 16; ++w)
                if (s_wred[w] > mv) { mv = s_wred[w]; mi = s_wri[w]; }
            s_tgt = mi;
        }
        // precompute target half of MLP L1: rows 512+64r .. 512+64r+64 of W1
        {
            const int u = tid & 63, part = tid >> 6;   // 8 parts x 8 rows
            float4 a = make_float4(0.f, 0.f, 0.f, 0.f);
            #pragma unroll
            for (int ii = 0; ii < 8; ++ii) {
                const int vr  = 64 * rank + part * 8 + ii;
                const float x = v_target[vr];
                const float4 w = __ldcs(&W14[(size_t)(NM + vr) * 64 + u]);  // no L1 pollution
                a.x += x * w.x; a.y += x * w.y; a.z += x * w.z; a.w += x * w.w;
            }
            ((float4*)s_p)[part * 64 + u] = a;
        }
        __syncthreads();
        if (tid < NH1) {
            float pj = 0.f;
            #pragma unroll
            for (int r = 0; r < 8; ++r) pj += s_p[r * NH1 + tid];
            s_p[tid] = pj;                 // stage for cluster exchange below
        }
        CLUSTER_SYNC();                    // mbarrier inits visible cluster-wide
        // one-time broadcast of target-half L1 partials into every CTA's s_hg row
        if (tid < NH1) {
            #pragma unroll
            for (int r = 0; r < CLN; ++r) {
                unsigned dst = mapa_u32(smem_u32(&s_hg[rank * NH1 + tid]), (unsigned)r);
                asm volatile("st.shared::cluster.f32 [%0], %1;" :: "r"(dst), "f"(s_p[tid]) : "memory");
            }
        }
        CLUSTER_SYNC();
        if (tid < NH1) {
            float h = 0.f;
            #pragma unroll
            for (int r = 0; r < CLN; ++r) h += s_hg[r * NH1 + tid];
            s_h1t[tid] = h;
        }
        CLUSTER_SYNC();                    // protect s_hg before step-0 reuse
    }
    grid_sync();   // publishes fp16 conversion + flag resets

    // ------------------------------------ scan ------------------------------------
    for (int s = 0; s < STEPS; ++s) {
        if (incl) {
            const int dn = s_done;               // done at step entry
            if (!dn) {
                // ---- (A) MLP L1, v half: CTA r covers v rows [64r, 64r+64) ----
                {
                    const int u = tid & 63, part = tid >> 6;
                    float4 a = make_float4(0.f, 0.f, 0.f, 0.f);
                    #pragma unroll
                    for (int ii = 0; ii < 8; ++ii) {
                        const int vr  = 64 * rank + part * 8 + ii;
                        const float x = s_v[vr];
                        const float4 w = __ldg(&W14[(size_t)vr * 64 + u]);
                        a.x += x * w.x; a.y += x * w.y; a.z += x * w.z; a.w += x * w.w;
                    }
                    ((float4*)s_p)[part * 64 + u] = a;
                }
                __syncthreads();
                if (tid < NH1) {               // one-sided push into CTA0 + tx signal
                    float pj = 0.f;
                    #pragma unroll
                    for (int r = 0; r < 8; ++r) pj += s_p[r * NH1 + tid];
                    unsigned dst = mapa_u32(smem_u32(&s_hg[rank * NH1 + tid]), 0u);
                    unsigned mb  = mapa_u32(smem_u32(&s_mbA), 0u);
                    st_async_b32(dst, __float_as_uint(pj), mb);
                }
                // ranks 1..7 do NOT wait — they fall through to the soft poll.

                // ---- (B) MLP tail + gumbel softmax + publish (CTA0 only) ----
                if (rank == 0) {
                    MBARRIER_WAIT_PARITY(smem_u32(&s_mbA), phA);
                    phA ^= 1;
                    if (tid == 0) MBARRIER_EXPECT_TX(smem_u32(&s_mbA), 8192u);
                    __syncthreads();
                    if (tid < NH1) {
                        float h = __ldg(&b1[tid]) + s_h1t[tid];
                        #pragma unroll
                        for (int r = 0; r < CLN; ++r) h += s_hg[r * NH1 + tid];
                        s_h1[tid] = fmaxf(h, 0.f);
                    }
                    __syncthreads();
                    {   // L2: 128 outs x 256 in, 16 parts x 16 rows  (W2 in L1)
                        const int u = tid & 31, part = tid >> 5;
                        float4 a = make_float4(0.f, 0.f, 0.f, 0.f);
                        #pragma unroll
                        for (int ii = 0; ii < 16; ++ii) {
                            const int i = part * 16 + ii;
                            const float hv = s_h1[i];
                            const float4 w = __ldg(&W24[(size_t)i * 32 + u]);
                            a.x += hv * w.x; a.y += hv * w.y; a.z += hv * w.z; a.w += hv * w.w;
                        }
                        ((float4*)s_p)[part * 32 + u] = a;
                    }
                    __syncthreads();
                    if (tid < NH2) {
                        float h = __ldg(&b2[tid]);
                        #pragma unroll
                        for (int p = 0; p < 16; ++p) h += s_p[p * NH2 + tid];
                        s_h2[tid] = fmaxf(h, 0.f);
                    }
                    __syncthreads();
                    {   // L3: 64 outs x 128 in, 32 parts x 4 rows  (W3 in L1)
                        const int u = tid & 15, part = tid >> 4;
                        float4 a = make_float4(0.f, 0.f, 0.f, 0.f);
                        #pragma unroll
                        for (int ii = 0; ii < 4; ++ii) {
                            const int i = part * 4 + ii;
                            const float hv = s_h2[i];
                            const float4 w = __ldg(&W34[(size_t)i * 16 + u]);
                            a.x += hv * w.x; a.y += hv * w.y; a.z += hv * w.z; a.w += hv * w.w;
                        }
                        ((float4*)s_p)[part * 16 + u] = a;
                    }
                    __syncthreads();
                    if (tid < NT) {
                        float lg = __ldg(&b3[tid]);
                        #pragma unroll
                        for (int p = 0; p < 32; ++p) lg += s_p[p * NT + tid];
                        out[NM + s * NT + tid] = lg;                    // not done here
                        s_sm[tid] = lg + __ldg(&gumbel[s * NT + tid]);  // TAU = 1
                    }
                    __syncthreads();
                    if (tid < 32) {   // parallel max
                        float m = fmaxf(s_sm[tid], s_sm[tid + 32]);
                        #pragma unroll
                        for (int off = 16; off > 0; off >>= 1)
                            m = fmaxf(m, __shfl_xor_sync(0xffffffffu, m, off));
                        if (tid == 0) s_scal = m;
                    }
                    __syncthreads();
                    if (tid < NT) s_sm[tid] = __expf(s_sm[tid] - s_scal);
                    __syncthreads();
                    if (tid < 32) {   // parallel sum
                        float ssum = s_sm[tid] + s_sm[tid + 32];
                        #pragma unroll
                        for (int off = 16; off > 0; off >>= 1)
                            ssum += __shfl_xor_sync(0xffffffffu, ssum, off);
                        if (tid == 0) s_scal = 1.f / ssum;
                    }
                    __syncthreads();
                    if (tid < NT) g_softv[s][tid] = s_sm[tid] * s_scal;
                    __syncthreads();   // HB: all g_softv stores visible to tid0's fence
                    if (tid == 0) {    // ONE cumulative fence (was 512 MEMBAR.GL)
                        g_softn[s] = NT;
                        __threadfence();
                        *(volatile unsigned*)&g_soft_seq = (unsigned)(s + 1);
                    }
                }
            } else {
                // ---- done: zero logits, frozen v, publish skip ----
                if (rank == 0) {
                    if (tid < NT) out[NM + s * NT + tid] = 0.f;
                    if (s == STEPS - 1) out[tid] = s_v[tid];
                    __syncthreads();
                    if (tid == 0) {
                        g_softn[s] = -1;
                        __threadfence();
                        *(volatile unsigned*)&g_soft_seq = (unsigned)(s + 1);
                    }
                }
            }
        }

        // ---- wait for soft publication (all blocks): volatile poll (proven fast) ----
        if (tid == 0) {
            while (*(volatile unsigned*)&g_soft_seq < (unsigned)(s + 1)) { }
            s_n = __ldcg(&g_softn[s]);
            __threadfence();
        }
        __syncthreads();
        const int n = s_n;

        // ---- Omega formation: 88 non-cluster blocks, fp16 operands, fp32 accumulate ----
        // Terms 0..CT-1 via __ldg stay L1-resident across steps; CT..63 stream (__ldcs).
        if (n >= 0 && !incl) {
            if (tid < NT) s_fv[tid] = __ldcg(&g_softv[s][tid]);
            __syncthreads();
            const int b2i   = bid - CLN;              // 0..87
            const int slice = b2i / BPS, w = b2i % BPS;
            const int base  = slice * 8192 + w * 744 + (w < 8 ? w : 8);
            const int cnt   = 744 + (w < 8 ? 1 : 0);
            const uint2* ob = (const uint2*)g_omh;
            for (int e = base + tid; e < base + cnt; e += NTHR) {
                float4 a0 = make_float4(0.f, 0.f, 0.f, 0.f);
                float4 a1 = a0, a2 = a0, a3 = a0;
                #pragma unroll
                for (int q = 0; q < CT; q += 4) {           // L1-resident strips
                    const float c0 = s_fv[q],     c1 = s_fv[q + 1];
                    const float c2 = s_fv[q + 2], c3 = s_fv[q + 3];
                    const float4 w0 = hf2f4(__ldg(ob + (size_t)(q)     * NM4 + e));
                    const float4 w1 = hf2f4(__ldg(ob + (size_t)(q + 1) * NM4 + e));
                    const float4 w2 = hf2f4(__ldg(ob + (size_t)(q + 2) * NM4 + e));
                    const float4 w3 = hf2f4(__ldg(ob + (size_t)(q + 3) * NM4 + e));
                    a0.x += c0 * w0.x; a0.y += c0 * w0.y; a0.z += c0 * w0.z; a0.w += c0 * w0.w;
                    a1.x += c1 * w1.x; a1.y += c1 * w1.y; a1.z += c1 * w1.z; a1.w += c1 * w1.w;
                    a2.x += c2 * w2.x; a2.y += c2 * w2.y; a2.z += c2 * w2.z; a2.w += c2 * w2.w;
                    a3.x += c3 * w3.x; a3.y += c3 * w3.y; a3.z += c3 * w3.z; a3.w += c3 * w3.w;
                }
                #pragma unroll
                for (int q = CT; q < NT; q += 4) {          // streaming strips
                    const float c0 = s_fv[q],     c1 = s_fv[q + 1];
                    const float c2 = s_fv[q + 2], c3 = s_fv[q + 3];
                    const float4 w0 = hf2f4(__ldcs(ob + (size_t)(q)     * NM4 + e));
                    const float4 w1 = hf2f4(__ldcs(ob + (size_t)(q + 1) * NM4 + e));
                    const float4 w2 = hf2f4(__ldcs(ob + (size_t)(q + 2) * NM4 + e));
                    const float4 w3 = hf2f4(__ldcs(ob + (size_t)(q + 3) * NM4 + e));
                    a0.x += c0 * w0.x; a0.y += c0 * w0.y; a0.z += c0 * w0.z; a0.w += c0 * w0.w;
                    a1.x += c1 * w1.x; a1.y += c1 * w1.y; a1.z += c1 * w1.z; a1.w += c1 * w1.w;
                    a2.x += c2 * w2.x; a2.y += c2 * w2.y; a2.z += c2 * w2.z; a2.w += c2 * w2.w;
                    a3.x += c3 * w3.x; a3.y += c3 * w3.y; a3.z += c3 * w3.z; a3.w += c3 * w3.w;
                }
                a0.x += a1.x + a2.x + a3.x; a0.y += a1.y + a2.y + a3.y;
                a0.z += a1.z + a2.z + a3.z; a0.w += a1.w + a2.w + a3.w;
                ((float4*)g_Omega)[e] = a0;
            }
            __syncthreads();                       // HB: all threads' stores before tid0
            if (tid == 0) {                        // ONE cumulative fence + arrival
                __threadfence();
                atomicAdd(&g_sdone[s][slice], 1u);
            }
        }

        // ---- Taylor action from registers (cluster 0, active steps only) ----
        if (incl && n >= 0) {
            if (tid == 0) {   // own 64-row slice ready (11 formation arrivals)
                while (*(volatile unsigned*)&g_sdone[s][rank] < (unsigned)BPS) { }
                __threadfence();
            }
            __syncthreads();
            float4 O[4][4];   // rows 64*rank + warp*4 + rr, cols lane*4 + 128*q
            {
                const float4* G4 = (const float4*)g_Omega;
                const int rbase = 64 * rank + warp * 4;
                #pragma unroll
                for (int rr = 0; rr < 4; ++rr)
                    #pragma unroll
                    for (int q = 0; q < 4; ++q)
                        O[rr][q] = __ldcg(&G4[(size_t)(rbase + rr) * 128 + lane + 32 * q]);
            }
            float accv = s_v[tid];

            #pragma unroll
            for (int k = 1; k <= NTAY; ++k) {
                const float4* src4 = (k == 1) ? (const float4*)s_v
                                              : (const float4*)s_t[(k - 1) & 1];
                const float4 t0 = src4[lane], t1 = src4[lane + 32],
                             t2 = src4[lane + 64], t3 = src4[lane + 96];
                const float invk = 1.0f / (float)k;
                #pragma unroll
                for (int rr = 0; rr < 4; ++rr) {
                    float p = O[rr][0].x * t0.x + O[rr][0].y * t0.y + O[rr][0].z * t0.z + O[rr][0].w * t0.w
                            + O[rr][1].x * t1.x + O[rr][1].y * t1.y + O[rr][1].z * t1.z + O[rr][1].w * t1.w
                            + O[rr][2].x * t2.x + O[rr][2].y * t2.y + O[rr][2].z * t2.z + O[rr][2].w * t2.w
                            + O[rr][3].x * t3.x + O[rr][3].y * t3.y + O[rr][3].z * t3.z + O[rr][3].w * t3.w;
                    #pragma unroll
                    for (int off = 16; off > 0; off >>= 1)
                        p += __shfl_down_sync(0xffffffffu, p, off);
                    if (lane == 0) s_brd[warp * 4 + rr] = p * invk;
                }
                __syncthreads();          // s_brd ready AND all reads of src4 done
                {   // one-sided exchange: value s_brd[m] -> rank (tid>>6), tx-signaled
                    const int m = tid & 63;
                    const unsigned dr = (unsigned)(tid >> 6);
                    const int buf = k & 1;
                    unsigned dst = mapa_u32(smem_u32(&s_t[buf][64 * rank + m]), dr);
                    unsigned mb  = mapa_u32(smem_u32(&s_mbX[buf]), dr);
                    st_async_b32(dst, __float_as_uint(s_brd[m]), mb);
                }
                {
                    const int buf = k & 1;
                    MBARRIER_WAIT_PARITY(smem_u32(&s_mbX[buf]), (buf ? ph1 : ph0));
                    if (buf) ph1 ^= 1; else ph0 ^= 1;
                    if (tid == 0) MBARRIER_EXPECT_TX(smem_u32(&s_mbX[buf]), 2048u);
                }
                __syncthreads();
                accv += s_t[k & 1][tid];
            }

            // ---- done_new = (argmax(v_new)==tgt); v = v_new (done was 0) ----
            const float vn = accv;
            {
                float bv = vn; int bi = tid;
                #pragma unroll
                for (int off = 16; off > 0; off >>= 1) {
                    float ov = __shfl_down_sync(0xffffffffu, bv, off);
                    int   oi = __shfl_down_sync(0xffffffffu, bi, off);
                    if (ov > bv) { bv = ov; bi = oi; }
                }
                if (lane == 0) { s_wred[warp] = bv; s_wri[warp] = bi; }
            }
            __syncthreads();
            s_v[tid] = vn;
            if (tid == 0) {
                float mv = s_wred[0]; int mi = s_wri[0];
                #pragma unroll
                for (int w = 1; w < 16; ++w)
                    if (s_wred[w] > mv) { mv = s_wred[w]; mi = s_wri[w]; }
                if (mi == s_tgt) s_done = 1;
            }
            __syncthreads();
            if (rank == 0 && s == STEPS - 1) out[tid] = vn;   // v_final
        }
    }
}

extern "C" void kernel_launch(void* const* d_in, const int* in_sizes, int n_in,
                              void* d_out, int out_size) {
    (void)in_sizes; (void)n_in; (void)out_size;
    const float* v_src    = (const float*)d_in[0];
    const float* v_target = (const float*)d_in[1];
    const float* omegas   = (const float*)d_in[2];
    const float* W1       = (const float*)d_in[3];
    const float* b1       = (const float*)d_in[4];
    const float* W2       = (const float*)d_in[5];
    const float* b2       = (const float*)d_in[6];
    const float* W3       = (const float*)d_in[7];
    const float* b3       = (const float*)d_in[8];
    const float* gumbel   = (const float*)d_in[9];
    float* out = (float*)d_out;

    petri_kernel<<<NBLK, NTHR>>>(v_src, v_target, omegas, W1, b1,
                                 W2, b2, W3, b3, gumbel, out);
}